// round 14
// baseline (speedup 1.0000x reference)
#include <cuda_runtime.h>
#include <cuda_fp16.h>
#include <math.h>
#include <cstdint>

constexpr int cB   = 2;
constexpr int cT   = 2048;
constexpr int cE   = 2048;
constexpr int cH   = 16;
constexpr int cKVH = 8;
constexpr int cD   = 128;

// Scratch (device globals). Half-precision operand buffers.
__device__ __half g_q   [(size_t)cB * cH   * cT * cD];   // (b,h,t,d) roped
__device__ __half g_k   [(size_t)cB * cKVH * cT * cD];   // (b,kvh,t,d) roped
__device__ __half g_vt  [(size_t)cB * cKVH * cD * cT];   // (b,kvh,d,t)
__device__ __half g_ao  [(size_t)cB * cT * cH * cD];     // (b,t,h,d)
__device__ __half g_xh  [(size_t)cB * cT * cE];          // x in half
// Concatenated transposed weights: rows [0,2048)=wq^T, [2048,3072)=wk^T, [3072,4096)=wv^T
__device__ __half g_wcat[(size_t)4096 * 2048];
__device__ __half g_wot [(size_t)2048 * 2048];

__device__ __forceinline__ uint32_t smem_u32(const void* p) {
    uint32_t a;
    asm("{ .reg .u64 t; cvta.to.shared.u64 t, %1; cvt.u32.u64 %0, t; }" : "=r"(a) : "l"(p));
    return a;
}

__device__ __forceinline__ void cp16(uint32_t dst, const void* src) {
    asm volatile("cp.async.cg.shared.global [%0], [%1], 16;"
                 :: "r"(dst), "l"(src) : "memory");
}

__device__ __forceinline__ unsigned packh2(float a, float b) {
    __half2 h = __floats2half2_rn(a, b);
    return *(unsigned*)&h;
}

// ---------------------------------------------------------------------------
__global__ __launch_bounds__(256) void quant_kernel(
    const float* __restrict__ x, __half* __restrict__ xh)
{
    const size_t i = ((size_t)blockIdx.x * 256 + threadIdx.x) * 4;
    float4 v = *(const float4*)(x + i);
    unsigned lo = packh2(v.x, v.y);
    unsigned hi = packh2(v.z, v.w);
    *(uint2*)(xh + i) = make_uint2(lo, hi);
}

// ---------------------------------------------------------------------------
__global__ __launch_bounds__(256) void wtrans_kernel(
    const float* __restrict__ W, __half* __restrict__ WT, int R, int Cc)
{
    __shared__ unsigned short t[32][33];
    const int x = blockIdx.x * 32 + threadIdx.x;
    const int y0 = blockIdx.y * 32 + threadIdx.y;
#pragma unroll
    for (int i = 0; i < 4; ++i) {
        __half h = __float2half_rn(W[(size_t)(y0 + i * 8) * Cc + x]);
        t[threadIdx.y + i * 8][threadIdx.x] = *(unsigned short*)&h;
    }
    __syncthreads();
    const int xo = blockIdx.y * 32 + threadIdx.x;
    const int yo0 = blockIdx.x * 32 + threadIdx.y;
#pragma unroll
    for (int i = 0; i < 4; ++i) {
        unsigned short v = t[threadIdx.x][threadIdx.y + i * 8];
        WT[(size_t)(yo0 + i * 8) * R + xo] = *(__half*)&v;
    }
}

// ---------------------------------------------------------------------------
// FP16 mma.sync GEMM v4 (unchanged from R13 — passing).
// ---------------------------------------------------------------------------
__device__ __forceinline__ void gemm4_load_stage(
    uint32_t sb, int s, int kt,
    const __half* __restrict__ A, const __half* __restrict__ BT,
    int rowBase, int colBase, int K, int lr, int lcc, int chS)
{
    const uint32_t aBase = sb + (uint32_t)s * 32768u;
    const uint32_t bBase = aBase + 16384u;
#pragma unroll
    for (int c = 0; c < 4; ++c) {
        const int row = lr + c * 32;
        cp16(aBase + (uint32_t)(row * 128 + chS * 16),
             A + (size_t)(rowBase + row) * K + kt + lcc * 8);
        cp16(bBase + (uint32_t)(row * 128 + chS * 16),
             BT + (size_t)(colBase + row) * K + kt + lcc * 8);
    }
    asm volatile("cp.async.commit_group;" ::: "memory");
}

__global__ __launch_bounds__(256) void fp16_gemm(
    const __half* __restrict__ A, const __half* __restrict__ BT,
    void* __restrict__ Cv,
    __half* __restrict__ Qo, __half* __restrict__ Ko, __half* __restrict__ Vo,
    int N, int K, int mode)
{
    extern __shared__ unsigned smp[];
    const uint32_t sb = smem_u32(smp);

    const int tid  = threadIdx.x;
    const int lane = tid & 31;
    const int w    = tid >> 5;
    const int wm   = (w >> 2) * 64;
    const int wn   = (w & 3) * 32;
    const int gr   = lane >> 2;
    const int gc   = lane & 3;

    const int rowBase = blockIdx.y * 128;
    const int colBase = blockIdx.x * 128;

    const int lr  = tid >> 3;
    const int lcc = tid & 7;
    const int chS = (lcc + (lr & 7)) & 7;

    float acc[4][4][4];
#pragma unroll
    for (int mi = 0; mi < 4; ++mi)
#pragma unroll
        for (int ni = 0; ni < 4; ++ni)
#pragma unroll
            for (int c = 0; c < 4; ++c) acc[mi][ni][c] = 0.f;

    const int nch = K / 64;
    gemm4_load_stage(sb, 0, 0,  A, BT, rowBase, colBase, K, lr, lcc, chS);
    gemm4_load_stage(sb, 1, 64, A, BT, rowBase, colBase, K, lr, lcc, chS);

    for (int ck = 0; ck < nch; ++ck) {
        const int s = ck % 3;
        if (ck + 2 < nch)
            asm volatile("cp.async.wait_group 1;" ::: "memory");
        else
            asm volatile("cp.async.wait_group 0;" ::: "memory");
        __syncthreads();
        if (ck + 2 < nch)
            gemm4_load_stage(sb, (ck + 2) % 3, (ck + 2) * 64,
                             A, BT, rowBase, colBase, K, lr, lcc, chS);

        const unsigned* As = smp + s * 8192;
        const unsigned* Bs = As + 4096;
#pragma unroll
        for (int kk = 0; kk < 64; kk += 16) {
            const int ch0 = kk >> 3;
            const int sw0 = (((ch0    ) + gr) & 7) * 4 + gc;
            const int sw1 = (((ch0 + 1) + gr) & 7) * 4 + gc;
            unsigned af[4][4], bf[4][2];
#pragma unroll
            for (int mi = 0; mi < 4; ++mi) {
                const int r = wm + mi * 16 + gr;
                af[mi][0] = As[r * 32 + sw0];
                af[mi][1] = As[(r + 8) * 32 + sw0];
                af[mi][2] = As[r * 32 + sw1];
                af[mi][3] = As[(r + 8) * 32 + sw1];
            }
#pragma unroll
            for (int ni = 0; ni < 4; ++ni) {
                const int rN = wn + ni * 8 + gr;
                bf[ni][0] = Bs[rN * 32 + sw0];
                bf[ni][1] = Bs[rN * 32 + sw1];
            }
#pragma unroll
            for (int mi = 0; mi < 4; ++mi)
#pragma unroll
                for (int ni = 0; ni < 4; ++ni) {
                    asm volatile(
                        "mma.sync.aligned.m16n8k16.row.col.f32.f16.f16.f32 "
                        "{%0,%1,%2,%3}, {%4,%5,%6,%7}, {%8,%9}, {%0,%1,%2,%3};"
                        : "+f"(acc[mi][ni][0]), "+f"(acc[mi][ni][1]),
                          "+f"(acc[mi][ni][2]), "+f"(acc[mi][ni][3])
                        : "r"(af[mi][0]), "r"(af[mi][1]),
                          "r"(af[mi][2]), "r"(af[mi][3]),
                          "r"(bf[ni][0]), "r"(bf[ni][1]));
                }
        }
    }

    if (mode == 0) {
        float* C = (float*)Cv;
#pragma unroll
        for (int mi = 0; mi < 4; ++mi)
#pragma unroll
            for (int ni = 0; ni < 4; ++ni) {
                const int row0 = rowBase + wm + mi * 16 + gr;
                const int col  = colBase + wn + ni * 8 + gc * 2;
                *(float2*)(C + (size_t)row0 * N + col) =
                    make_float2(acc[mi][ni][0], acc[mi][ni][1]);
                *(float2*)(C + (size_t)(row0 + 8) * N + col) =
                    make_float2(acc[mi][ni][2], acc[mi][ni][3]);
            }
        return;
    }

    const int hcat = colBase >> 7;
    if (hcat < 24) {
        __half* OutP = (hcat < 16) ? Qo : Ko;
        const int HH  = (hcat < 16) ? cH : cKVH;
        const int h   = (hcat < 16) ? hcat : hcat - 16;
#pragma unroll
        for (int mi = 0; mi < 4; ++mi)
#pragma unroll
            for (int ni = 0; ni < 4; ++ni) {
                const int row0 = rowBase + wm + mi * 16 + gr;
                const int col  = colBase + wn + ni * 8 + gc * 2;
                const int d = col & (cD - 1);
                const int j = d >> 1;
                const float inv = exp2f(-13.287712379549449f * (float)j * (1.0f / 64.0f));
#pragma unroll
                for (int rr = 0; rr < 2; ++rr) {
                    const int row = row0 + rr * 8;
                    const int b = row >> 11;
                    const int t = row & (cT - 1);
                    float sn, cs;
                    sincosf((float)t * inv, &sn, &cs);
                    const float x0 = acc[mi][ni][rr*2];
                    const float x1 = acc[mi][ni][rr*2+1];
                    __half* p = OutP + ((size_t)(b * HH + h) * cT + t) * cD + d;
                    *(unsigned*)p = packh2(x0 * cs - x1 * sn, x0 * sn + x1 * cs);
                }
            }
    } else {
        const int h = hcat - 24;
#pragma unroll
        for (int mi = 0; mi < 4; ++mi)
#pragma unroll
            for (int ni = 0; ni < 4; ++ni) {
                const int row0 = rowBase + wm + mi * 16 + gr;
                const int col  = colBase + wn + ni * 8 + gc * 2;
                const int d = col & (cD - 1);
#pragma unroll
                for (int rr = 0; rr < 2; ++rr) {
                    const int row = row0 + rr * 8;
                    const int b = row >> 11;
                    const int t = row & (cT - 1);
                    __half* p = Vo + ((size_t)(b * cKVH + h) * cD + d) * cT + t;
                    p[0]  = __float2half_rn(acc[mi][ni][rr*2]);
                    p[cT] = __float2half_rn(acc[mi][ni][rr*2+1]);
                }
            }
    }
}

// ---------------------------------------------------------------------------
// FP16 flash attention v2: P in registers (C->A fragment identity),
// double-buffered K/V with cp.async prefetch, LPT qb ordering.
// smem: Qs 128x68w + 2x Ks 64x68w + 2x Vs 128x36w = 26624 w = 104 KB
// ---------------------------------------------------------------------------
__global__ __launch_bounds__(256) void attn_kernel(
    const __half* __restrict__ Q, const __half* __restrict__ K,
    const __half* __restrict__ VT, __half* __restrict__ AO)
{
    extern __shared__ unsigned sm[];
    unsigned* Qs    = sm;                          // [128][68]
    unsigned* KsB[2] = { sm + 8704, sm + 8704 + 4352 };
    unsigned* VsB[2] = { sm + 8704 + 8704, sm + 8704 + 8704 + 4608 };
    const uint32_t sQ  = smem_u32(Qs);
    const uint32_t sK0 = smem_u32(KsB[0]);
    const uint32_t sK1 = smem_u32(KsB[1]);
    const uint32_t sV0 = smem_u32(VsB[0]);
    const uint32_t sV1 = smem_u32(VsB[1]);
    const uint32_t sKArr[2] = { sK0, sK1 };
    const uint32_t sVArr[2] = { sV0, sV1 };

    const int bid = blockIdx.x;
    const int qb  = 15 - (bid & 15);               // LPT: heavy blocks first
    const int h   = (bid >> 4) & 15;
    const int b   = bid >> 8;
    const int kvh = h >> 1;

    const __half* qptr  = Q  + ((size_t)(b * cH + h) * cT + qb * 128) * cD;
    const __half* kbase = K  + (size_t)(b * cKVH + kvh) * cT * cD;
    const __half* vbase = VT + (size_t)(b * cKVH + kvh) * cD * cT;

    const int tid  = threadIdx.x;
    const int lane = tid & 31;
    const int w    = tid >> 5;
    const int gr   = lane >> 2;
    const int gc   = lane & 3;
    const int wrow = w * 16;

    // Q fill
#pragma unroll
    for (int it = 0; it < 8; ++it) {
        const int i = tid + it * 256;
        const int r = i >> 4, c16 = i & 15;
        cp16(sQ + (uint32_t)(r * 272 + c16 * 16), qptr + (size_t)r * cD + c16 * 8);
    }
    asm volatile("cp.async.commit_group;" ::: "memory");

    const int nkv = 2 * qb + 2;

    // prologue: K/V tile 0 -> buffer 0
    {
        const __half* kp = kbase;
        const __half* vp = vbase;
#pragma unroll
        for (int it = 0; it < 4; ++it) {
            const int i = tid + it * 256;
            {
                const int r = i >> 4, c16 = i & 15;
                cp16(sK0 + (uint32_t)(r * 272 + c16 * 16), kp + (size_t)r * cD + c16 * 8);
            }
            {
                const int d = i >> 3, c8 = i & 7;
                cp16(sV0 + (uint32_t)(d * 144 + c8 * 16), vp + (size_t)d * cT + c8 * 8);
            }
        }
        asm volatile("cp.async.commit_group;" ::: "memory");
    }

    float m0 = -1e30f, m1 = -1e30f, l0 = 0.f, l1 = 0.f;
    float oacc[16][4];
#pragma unroll
    for (int ni = 0; ni < 16; ++ni)
#pragma unroll
        for (int c = 0; c < 4; ++c) oacc[ni][c] = 0.f;

    const float sc = 0.08838834764831845f * 1.4426950408889634f;
    const int qrow0 = qb * 128;

    for (int kt = 0; kt < nkv; ++kt) {
        asm volatile("cp.async.wait_group 0;" ::: "memory");
        __syncthreads();

        // prefetch next tile into the other buffer (overlaps with compute)
        if (kt + 1 < nkv) {
            const int nb = (kt + 1) & 1;
            const __half* kp = kbase + (size_t)(kt + 1) * 64 * cD;
            const __half* vp = vbase + (kt + 1) * 64;
            const uint32_t dK = sKArr[nb];
            const uint32_t dV = sVArr[nb];
#pragma unroll
            for (int it = 0; it < 4; ++it) {
                const int i = tid + it * 256;
                {
                    const int r = i >> 4, c16 = i & 15;
                    cp16(dK + (uint32_t)(r * 272 + c16 * 16), kp + (size_t)r * cD + c16 * 8);
                }
                {
                    const int d = i >> 3, c8 = i & 7;
                    cp16(dV + (uint32_t)(d * 144 + c8 * 16), vp + (size_t)d * cT + c8 * 8);
                }
            }
            asm volatile("cp.async.commit_group;" ::: "memory");
        }

        const unsigned* Ks = KsB[kt & 1];
        const unsigned* Vs = VsB[kt & 1];

        // S = Q K^T
        float s[8][4];
#pragma unroll
        for (int ni = 0; ni < 8; ++ni)
#pragma unroll
            for (int c = 0; c < 4; ++c) s[ni][c] = 0.f;

#pragma unroll
        for (int kk = 0; kk < 128; kk += 16) {
            const int wb = kk >> 1;
            unsigned a0 = Qs[(wrow + gr    ) * 68 + wb + gc    ];
            unsigned a1 = Qs[(wrow + gr + 8) * 68 + wb + gc    ];
            unsigned a2 = Qs[(wrow + gr    ) * 68 + wb + gc + 4];
            unsigned a3 = Qs[(wrow + gr + 8) * 68 + wb + gc + 4];
#pragma unroll
            for (int ni = 0; ni < 8; ++ni) {
                unsigned b0 = Ks[(ni * 8 + gr) * 68 + wb + gc    ];
                unsigned b1 = Ks[(ni * 8 + gr) * 68 + wb + gc + 4];
                asm volatile(
                    "mma.sync.aligned.m16n8k16.row.col.f32.f16.f16.f32 "
                    "{%0,%1,%2,%3}, {%4,%5,%6,%7}, {%8,%9}, {%0,%1,%2,%3};"
                    : "+f"(s[ni][0]), "+f"(s[ni][1]), "+f"(s[ni][2]), "+f"(s[ni][3])
                    : "r"(a0), "r"(a1), "r"(a2), "r"(a3), "r"(b0), "r"(b1));
            }
        }

        // mask + scale (log2 domain)
        const bool diag = (kt >= 2 * qb);
        const int r0g = qrow0 + wrow + gr;
        const int r1g = r0g + 8;
#pragma unroll
        for (int ni = 0; ni < 8; ++ni) {
            const int col = kt * 64 + ni * 8 + gc * 2;
            s[ni][0] = (diag && col     > r0g) ? -1e30f : s[ni][0] * sc;
            s[ni][1] = (diag && col + 1 > r0g) ? -1e30f : s[ni][1] * sc;
            s[ni][2] = (diag && col     > r1g) ? -1e30f : s[ni][2] * sc;
            s[ni][3] = (diag && col + 1 > r1g) ? -1e30f : s[ni][3] * sc;
        }

        float mx0 = -1e30f, mx1 = -1e30f;
#pragma unroll
        for (int ni = 0; ni < 8; ++ni) {
            mx0 = fmaxf(mx0, fmaxf(s[ni][0], s[ni][1]));
            mx1 = fmaxf(mx1, fmaxf(s[ni][2], s[ni][3]));
        }
        mx0 = fmaxf(mx0, __shfl_xor_sync(0xffffffffu, mx0, 1));
        mx0 = fmaxf(mx0, __shfl_xor_sync(0xffffffffu, mx0, 2));
        mx1 = fmaxf(mx1, __shfl_xor_sync(0xffffffffu, mx1, 1));
        mx1 = fmaxf(mx1, __shfl_xor_sync(0xffffffffu, mx1, 2));

        const float mn0 = fmaxf(m0, mx0);
        const float mn1 = fmaxf(m1, mx1);
        const float cr0 = exp2f(m0 - mn0);
        const float cr1 = exp2f(m1 - mn1);
        m0 = mn0; m1 = mn1;

        // exp + pack P into A-fragment registers (no smem roundtrip)
        unsigned pp[8][2];
        float ls0 = 0.f, ls1 = 0.f;
#pragma unroll
        for (int ni = 0; ni < 8; ++ni) {
            float p0 = exp2f(s[ni][0] - mn0);
            float p1 = exp2f(s[ni][1] - mn0);
            float p2 = exp2f(s[ni][2] - mn1);
            float p3 = exp2f(s[ni][3] - mn1);
            ls0 += p0 + p1;
            ls1 += p2 + p3;
            pp[ni][0] = packh2(p0, p1);
            pp[ni][1] = packh2(p2, p3);
        }
        ls0 += __shfl_xor_sync(0xffffffffu, ls0, 1);
        ls0 += __shfl_xor_sync(0xffffffffu, ls0, 2);
        ls1 += __shfl_xor_sync(0xffffffffu, ls1, 1);
        ls1 += __shfl_xor_sync(0xffffffffu, ls1, 2);
        l0 = l0 * cr0 + ls0;
        l1 = l1 * cr1 + ls1;

#pragma unroll
        for (int ni = 0; ni < 16; ++ni) {
            oacc[ni][0] *= cr0; oacc[ni][1] *= cr0;
            oacc[ni][2] *= cr1; oacc[ni][3] *= cr1;
        }

        // O += P V : P from registers, V^T from smem
#pragma unroll
        for (int kk = 0; kk < 64; kk += 16) {
            const int wb = kk >> 1;
            const int f0 = kk >> 3;          // 0,2,4,6
            unsigned a0 = pp[f0][0];
            unsigned a1 = pp[f0][1];
            unsigned a2 = pp[f0 + 1][0];
            unsigned a3 = pp[f0 + 1][1];
#pragma unroll
            for (int ni = 0; ni < 16; ++ni) {
                unsigned b0 = Vs[(ni * 8 + gr) * 36 + wb + gc    ];
                unsigned b1 = Vs[(ni * 8 + gr) * 36 + wb + gc + 4];
                asm volatile(
                    "mma.sync.aligned.m16n8k16.row.col.f32.f16.f16.f32 "
                    "{%0,%1,%2,%3}, {%4,%5,%6,%7}, {%8,%9}, {%0,%1,%2,%3};"
                    : "+f"(oacc[ni][0]), "+f"(oacc[ni][1]),
                      "+f"(oacc[ni][2]), "+f"(oacc[ni][3])
                    : "r"(a0), "r"(a1), "r"(a2), "r"(a3), "r"(b0), "r"(b1));
            }
        }
    }

    const float i0 = 1.f / l0;
    const float i1 = 1.f / l1;
    const int t0 = qrow0 + wrow + gr;
#pragma unroll
    for (int ni = 0; ni < 16; ++ni) {
        const int d = ni * 8 + gc * 2;
        __half* p0 = AO + ((size_t)(b * cT + t0    ) * cH + h) * cD + d;
        __half* p1 = AO + ((size_t)(b * cT + t0 + 8) * cH + h) * cD + d;
        *(unsigned*)p0 = packh2(oacc[ni][0] * i0, oacc[ni][1] * i0);
        *(unsigned*)p1 = packh2(oacc[ni][2] * i1, oacc[ni][3] * i1);
    }
}

// ---------------------------------------------------------------------------
extern "C" void kernel_launch(void* const* d_in, const int* in_sizes, int n_in,
                              void* d_out, int out_size)
{
    const float* x  = (const float*)d_in[0];
    const float* wq = (const float*)d_in[2];
    const float* wk = (const float*)d_in[3];
    const float* wv = (const float*)d_in[4];
    const float* wo = (const float*)d_in[5];
    float* out = (float*)d_out;

    void *pq, *pk, *pv, *pao, *pxh, *pwc, *pwo;
    cudaGetSymbolAddress(&pq,  g_q);
    cudaGetSymbolAddress(&pk,  g_k);
    cudaGetSymbolAddress(&pv,  g_vt);
    cudaGetSymbolAddress(&pao, g_ao);
    cudaGetSymbolAddress(&pxh, g_xh);
    cudaGetSymbolAddress(&pwc, g_wcat);
    cudaGetSymbolAddress(&pwo, g_wot);
    __half* q    = (__half*)pq;
    __half* k    = (__half*)pk;
    __half* vt   = (__half*)pv;
    __half* ao   = (__half*)pao;
    __half* xh   = (__half*)pxh;
    __half* wcat = (__half*)pwc;
    __half* wot  = (__half*)pwo;

    const int M = cB * cT;  // 4096

    quant_kernel<<<(int)(((size_t)M * cE / 4) / 256), 256>>>(x, xh);
    wtrans_kernel<<<dim3(2048 / 32, 2048 / 32), dim3(32, 8)>>>(wq, wcat, 2048, 2048);
    wtrans_kernel<<<dim3(1024 / 32, 2048 / 32), dim3(32, 8)>>>(wk, wcat + (size_t)2048 * 2048, 2048, 1024);
    wtrans_kernel<<<dim3(1024 / 32, 2048 / 32), dim3(32, 8)>>>(wv, wcat + (size_t)3072 * 2048, 2048, 1024);
    wtrans_kernel<<<dim3(2048 / 32, 2048 / 32), dim3(32, 8)>>>(wo, wot, 2048, 2048);

    const int gemm_smem = 3 * 32768;  // 98304 -> 2 CTAs/SM
    cudaFuncSetAttribute(fp16_gemm, cudaFuncAttributeMaxDynamicSharedMemorySize, gemm_smem);

    // Fused QKV projection
    fp16_gemm<<<dim3(32, 32), 256, gemm_smem>>>(xh, wcat, nullptr, q, k, vt, 4096, cE, 3);

    const int attn_smem = (128 * 68 + 2 * 64 * 68 + 2 * 128 * 36) * 4;  // 106496
    cudaFuncSetAttribute(attn_kernel, cudaFuncAttributeMaxDynamicSharedMemorySize, attn_smem);
    attn_kernel<<<cB * cH * (cT / 128), 256, attn_smem>>>(q, k, vt, ao);

    // Output projection
    fp16_gemm<<<dim3(16, 32), 256, gemm_smem>>>(ao, wot, out, nullptr, nullptr, nullptr, cE, cE, 0);
}

// round 16
// speedup vs baseline: 1.5127x; 1.5127x over previous
#include <cuda_runtime.h>
#include <cuda_fp16.h>
#include <math.h>
#include <cstdint>

constexpr int cB   = 2;
constexpr int cT   = 2048;
constexpr int cE   = 2048;
constexpr int cH   = 16;
constexpr int cKVH = 8;
constexpr int cD   = 128;

// Scratch (device globals). Half-precision operand buffers.
__device__ __half g_q   [(size_t)cB * cH   * cT * cD];   // (b,h,t,d) roped
__device__ __half g_k   [(size_t)cB * cKVH * cT * cD];   // (b,kvh,t,d) roped
__device__ __half g_vt  [(size_t)cB * cKVH * cD * cT];   // (b,kvh,d,t)
__device__ __half g_ao  [(size_t)cB * cT * cH * cD];     // (b,t,h,d)
__device__ __half g_xh  [(size_t)cB * cT * cE];          // x in half
// Concatenated transposed weights: rows [0,2048)=wq^T, [2048,3072)=wk^T, [3072,4096)=wv^T
__device__ __half g_wcat[(size_t)4096 * 2048];
__device__ __half g_wot [(size_t)2048 * 2048];

__device__ __forceinline__ uint32_t smem_u32(const void* p) {
    uint32_t a;
    asm("{ .reg .u64 t; cvta.to.shared.u64 t, %1; cvt.u32.u64 %0, t; }" : "=r"(a) : "l"(p));
    return a;
}

__device__ __forceinline__ void cp16(uint32_t dst, const void* src) {
    asm volatile("cp.async.cg.shared.global [%0], [%1], 16;"
                 :: "r"(dst), "l"(src) : "memory");
}

__device__ __forceinline__ unsigned packh2(float a, float b) {
    __half2 h = __floats2half2_rn(a, b);
    return *(unsigned*)&h;
}

// ---------------------------------------------------------------------------
__global__ __launch_bounds__(256) void quant_kernel(
    const float* __restrict__ x, __half* __restrict__ xh)
{
    const size_t i = ((size_t)blockIdx.x * 256 + threadIdx.x) * 4;
    float4 v = *(const float4*)(x + i);
    unsigned lo = packh2(v.x, v.y);
    unsigned hi = packh2(v.z, v.w);
    *(uint2*)(xh + i) = make_uint2(lo, hi);
}

// ---------------------------------------------------------------------------
__global__ __launch_bounds__(256) void wtrans_kernel(
    const float* __restrict__ W, __half* __restrict__ WT, int R, int Cc)
{
    __shared__ unsigned short t[32][33];
    const int x = blockIdx.x * 32 + threadIdx.x;
    const int y0 = blockIdx.y * 32 + threadIdx.y;
#pragma unroll
    for (int i = 0; i < 4; ++i) {
        __half h = __float2half_rn(W[(size_t)(y0 + i * 8) * Cc + x]);
        t[threadIdx.y + i * 8][threadIdx.x] = *(unsigned short*)&h;
    }
    __syncthreads();
    const int xo = blockIdx.y * 32 + threadIdx.x;
    const int yo0 = blockIdx.x * 32 + threadIdx.y;
#pragma unroll
    for (int i = 0; i < 4; ++i) {
        unsigned short v = t[threadIdx.x][threadIdx.y + i * 8];
        WT[(size_t)(yo0 + i * 8) * R + xo] = *(__half*)&v;
    }
}

// ---------------------------------------------------------------------------
// FP16 mma.sync GEMM v4 (R13 — passing, 2 CTA/SM).
// ---------------------------------------------------------------------------
__device__ __forceinline__ void gemm4_load_stage(
    uint32_t sb, int s, int kt,
    const __half* __restrict__ A, const __half* __restrict__ BT,
    int rowBase, int colBase, int K, int lr, int lcc, int chS)
{
    const uint32_t aBase = sb + (uint32_t)s * 32768u;
    const uint32_t bBase = aBase + 16384u;
#pragma unroll
    for (int c = 0; c < 4; ++c) {
        const int row = lr + c * 32;
        cp16(aBase + (uint32_t)(row * 128 + chS * 16),
             A + (size_t)(rowBase + row) * K + kt + lcc * 8);
        cp16(bBase + (uint32_t)(row * 128 + chS * 16),
             BT + (size_t)(colBase + row) * K + kt + lcc * 8);
    }
    asm volatile("cp.async.commit_group;" ::: "memory");
}

__global__ __launch_bounds__(256) void fp16_gemm(
    const __half* __restrict__ A, const __half* __restrict__ BT,
    void* __restrict__ Cv,
    __half* __restrict__ Qo, __half* __restrict__ Ko, __half* __restrict__ Vo,
    int N, int K, int mode)
{
    extern __shared__ unsigned smp[];
    const uint32_t sb = smem_u32(smp);

    const int tid  = threadIdx.x;
    const int lane = tid & 31;
    const int w    = tid >> 5;
    const int wm   = (w >> 2) * 64;
    const int wn   = (w & 3) * 32;
    const int gr   = lane >> 2;
    const int gc   = lane & 3;

    const int rowBase = blockIdx.y * 128;
    const int colBase = blockIdx.x * 128;

    const int lr  = tid >> 3;
    const int lcc = tid & 7;
    const int chS = (lcc + (lr & 7)) & 7;

    float acc[4][4][4];
#pragma unroll
    for (int mi = 0; mi < 4; ++mi)
#pragma unroll
        for (int ni = 0; ni < 4; ++ni)
#pragma unroll
            for (int c = 0; c < 4; ++c) acc[mi][ni][c] = 0.f;

    const int nch = K / 64;
    gemm4_load_stage(sb, 0, 0,  A, BT, rowBase, colBase, K, lr, lcc, chS);
    gemm4_load_stage(sb, 1, 64, A, BT, rowBase, colBase, K, lr, lcc, chS);

    for (int ck = 0; ck < nch; ++ck) {
        const int s = ck % 3;
        if (ck + 2 < nch)
            asm volatile("cp.async.wait_group 1;" ::: "memory");
        else
            asm volatile("cp.async.wait_group 0;" ::: "memory");
        __syncthreads();
        if (ck + 2 < nch)
            gemm4_load_stage(sb, (ck + 2) % 3, (ck + 2) * 64,
                             A, BT, rowBase, colBase, K, lr, lcc, chS);

        const unsigned* As = smp + s * 8192;
        const unsigned* Bs = As + 4096;
#pragma unroll
        for (int kk = 0; kk < 64; kk += 16) {
            const int ch0 = kk >> 3;
            const int sw0 = (((ch0    ) + gr) & 7) * 4 + gc;
            const int sw1 = (((ch0 + 1) + gr) & 7) * 4 + gc;
            unsigned af[4][4], bf[4][2];
#pragma unroll
            for (int mi = 0; mi < 4; ++mi) {
                const int r = wm + mi * 16 + gr;
                af[mi][0] = As[r * 32 + sw0];
                af[mi][1] = As[(r + 8) * 32 + sw0];
                af[mi][2] = As[r * 32 + sw1];
                af[mi][3] = As[(r + 8) * 32 + sw1];
            }
#pragma unroll
            for (int ni = 0; ni < 4; ++ni) {
                const int rN = wn + ni * 8 + gr;
                bf[ni][0] = Bs[rN * 32 + sw0];
                bf[ni][1] = Bs[rN * 32 + sw1];
            }
#pragma unroll
            for (int mi = 0; mi < 4; ++mi)
#pragma unroll
                for (int ni = 0; ni < 4; ++ni) {
                    asm volatile(
                        "mma.sync.aligned.m16n8k16.row.col.f32.f16.f16.f32 "
                        "{%0,%1,%2,%3}, {%4,%5,%6,%7}, {%8,%9}, {%0,%1,%2,%3};"
                        : "+f"(acc[mi][ni][0]), "+f"(acc[mi][ni][1]),
                          "+f"(acc[mi][ni][2]), "+f"(acc[mi][ni][3])
                        : "r"(af[mi][0]), "r"(af[mi][1]),
                          "r"(af[mi][2]), "r"(af[mi][3]),
                          "r"(bf[ni][0]), "r"(bf[ni][1]));
                }
        }
    }

    if (mode == 0) {
        float* C = (float*)Cv;
#pragma unroll
        for (int mi = 0; mi < 4; ++mi)
#pragma unroll
            for (int ni = 0; ni < 4; ++ni) {
                const int row0 = rowBase + wm + mi * 16 + gr;
                const int col  = colBase + wn + ni * 8 + gc * 2;
                *(float2*)(C + (size_t)row0 * N + col) =
                    make_float2(acc[mi][ni][0], acc[mi][ni][1]);
                *(float2*)(C + (size_t)(row0 + 8) * N + col) =
                    make_float2(acc[mi][ni][2], acc[mi][ni][3]);
            }
        return;
    }

    const int hcat = colBase >> 7;
    if (hcat < 24) {
        __half* OutP = (hcat < 16) ? Qo : Ko;
        const int HH  = (hcat < 16) ? cH : cKVH;
        const int h   = (hcat < 16) ? hcat : hcat - 16;
#pragma unroll
        for (int mi = 0; mi < 4; ++mi)
#pragma unroll
            for (int ni = 0; ni < 4; ++ni) {
                const int row0 = rowBase + wm + mi * 16 + gr;
                const int col  = colBase + wn + ni * 8 + gc * 2;
                const int d = col & (cD - 1);
                const int j = d >> 1;
                const float inv = exp2f(-13.287712379549449f * (float)j * (1.0f / 64.0f));
#pragma unroll
                for (int rr = 0; rr < 2; ++rr) {
                    const int row = row0 + rr * 8;
                    const int b = row >> 11;
                    const int t = row & (cT - 1);
                    float sn, cs;
                    sincosf((float)t * inv, &sn, &cs);
                    const float x0 = acc[mi][ni][rr*2];
                    const float x1 = acc[mi][ni][rr*2+1];
                    __half* p = OutP + ((size_t)(b * HH + h) * cT + t) * cD + d;
                    *(unsigned*)p = packh2(x0 * cs - x1 * sn, x0 * sn + x1 * cs);
                }
            }
    } else {
        const int h = hcat - 24;
#pragma unroll
        for (int mi = 0; mi < 4; ++mi)
#pragma unroll
            for (int ni = 0; ni < 4; ++ni) {
                const int row0 = rowBase + wm + mi * 16 + gr;
                const int col  = colBase + wn + ni * 8 + gc * 2;
                const int d = col & (cD - 1);
#pragma unroll
                for (int rr = 0; rr < 2; ++rr) {
                    const int row = row0 + rr * 8;
                    const int b = row >> 11;
                    const int t = row & (cT - 1);
                    __half* p = Vo + ((size_t)(b * cKVH + h) * cD + d) * cT + t;
                    p[0]  = __float2half_rn(acc[mi][ni][rr*2]);
                    p[cT] = __float2half_rn(acc[mi][ni][rr*2+1]);
                }
            }
    }
}

// ---------------------------------------------------------------------------
// FP16 flash attention — exact R13 version (598 µs baseline) + LPT remap only.
// smem: Qs 128x68w + Ks 64x68w + Vs 128x36w + Ps 128x36w = 87.3 KB
// ---------------------------------------------------------------------------
__global__ __launch_bounds__(256) void attn_kernel(
    const __half* __restrict__ Q, const __half* __restrict__ K,
    const __half* __restrict__ VT, __half* __restrict__ AO)
{
    extern __shared__ unsigned sm[];
    unsigned* Qs = sm;                        // [128][68] words
    unsigned* Ks = Qs + 128 * 68;             // [64][68]
    unsigned* Vs = Ks + 64 * 68;              // [128][36]
    unsigned* Ps = Vs + 128 * 36;             // [128][36]
    const uint32_t sQ = smem_u32(Qs);
    const uint32_t sK = smem_u32(Ks);
    const uint32_t sV = smem_u32(Vs);

    const int bid = blockIdx.x;
    const int qb  = 15 - (bid & 15);          // LPT: heavy q-blocks first
    const int h   = (bid >> 4) & 15;
    const int b   = bid >> 8;
    const int kvh = h >> 1;

    const __half* qptr  = Q  + ((size_t)(b * cH + h) * cT + qb * 128) * cD;
    const __half* kbase = K  + (size_t)(b * cKVH + kvh) * cT * cD;
    const __half* vbase = VT + (size_t)(b * cKVH + kvh) * cD * cT;

    const int tid  = threadIdx.x;
    const int lane = tid & 31;
    const int w    = tid >> 5;
    const int gr   = lane >> 2;
    const int gc   = lane & 3;
    const int wrow = w * 16;

#pragma unroll
    for (int it = 0; it < 8; ++it) {
        const int i = tid + it * 256;
        const int r = i >> 4, c16 = i & 15;
        cp16(sQ + (uint32_t)(r * 272 + c16 * 16), qptr + (size_t)r * cD + c16 * 8);
    }
    asm volatile("cp.async.commit_group;" ::: "memory");

    float m0 = -1e30f, m1 = -1e30f, l0 = 0.f, l1 = 0.f;
    float oacc[16][4];
#pragma unroll
    for (int ni = 0; ni < 16; ++ni)
#pragma unroll
        for (int c = 0; c < 4; ++c) oacc[ni][c] = 0.f;

    const float sc = 0.08838834764831845f * 1.4426950408889634f;
    const int qrow0 = qb * 128;
    const int nkv = 2 * qb + 2;

    for (int kt = 0; kt < nkv; ++kt) {
        __syncthreads();
        const __half* kp = kbase + (size_t)kt * 64 * cD;
        const __half* vp = vbase + kt * 64;
#pragma unroll
        for (int it = 0; it < 4; ++it) {
            const int i = tid + it * 256;
            {
                const int r = i >> 4, c16 = i & 15;
                cp16(sK + (uint32_t)(r * 272 + c16 * 16), kp + (size_t)r * cD + c16 * 8);
            }
            {
                const int d = i >> 3, c8 = i & 7;
                cp16(sV + (uint32_t)(d * 144 + c8 * 16), vp + (size_t)d * cT + c8 * 8);
            }
        }
        asm volatile("cp.async.commit_group;" ::: "memory");
        asm volatile("cp.async.wait_group 0;" ::: "memory");
        __syncthreads();

        float s[8][4];
#pragma unroll
        for (int ni = 0; ni < 8; ++ni)
#pragma unroll
            for (int c = 0; c < 4; ++c) s[ni][c] = 0.f;

#pragma unroll
        for (int kk = 0; kk < 128; kk += 16) {
            const int wb = kk >> 1;
            unsigned a0 = Qs[(wrow + gr    ) * 68 + wb + gc    ];
            unsigned a1 = Qs[(wrow + gr + 8) * 68 + wb + gc    ];
            unsigned a2 = Qs[(wrow + gr    ) * 68 + wb + gc + 4];
            unsigned a3 = Qs[(wrow + gr + 8) * 68 + wb + gc + 4];
#pragma unroll
            for (int ni = 0; ni < 8; ++ni) {
                unsigned b0 = Ks[(ni * 8 + gr) * 68 + wb + gc    ];
                unsigned b1 = Ks[(ni * 8 + gr) * 68 + wb + gc + 4];
                asm volatile(
                    "mma.sync.aligned.m16n8k16.row.col.f32.f16.f16.f32 "
                    "{%0,%1,%2,%3}, {%4,%5,%6,%7}, {%8,%9}, {%0,%1,%2,%3};"
                    : "+f"(s[ni][0]), "+f"(s[ni][1]), "+f"(s[ni][2]), "+f"(s[ni][3])
                    : "r"(a0), "r"(a1), "r"(a2), "r"(a3), "r"(b0), "r"(b1));
            }
        }

        const bool diag = (kt >= 2 * qb);
        const int r0g = qrow0 + wrow + gr;
        const int r1g = r0g + 8;
#pragma unroll
        for (int ni = 0; ni < 8; ++ni) {
            const int col = kt * 64 + ni * 8 + gc * 2;
            s[ni][0] = (diag && col     > r0g) ? -1e30f : s[ni][0] * sc;
            s[ni][1] = (diag && col + 1 > r0g) ? -1e30f : s[ni][1] * sc;
            s[ni][2] = (diag && col     > r1g) ? -1e30f : s[ni][2] * sc;
            s[ni][3] = (diag && col + 1 > r1g) ? -1e30f : s[ni][3] * sc;
        }

        float mx0 = -1e30f, mx1 = -1e30f;
#pragma unroll
        for (int ni = 0; ni < 8; ++ni) {
            mx0 = fmaxf(mx0, fmaxf(s[ni][0], s[ni][1]));
            mx1 = fmaxf(mx1, fmaxf(s[ni][2], s[ni][3]));
        }
        mx0 = fmaxf(mx0, __shfl_xor_sync(0xffffffffu, mx0, 1));
        mx0 = fmaxf(mx0, __shfl_xor_sync(0xffffffffu, mx0, 2));
        mx1 = fmaxf(mx1, __shfl_xor_sync(0xffffffffu, mx1, 1));
        mx1 = fmaxf(mx1, __shfl_xor_sync(0xffffffffu, mx1, 2));

        const float mn0 = fmaxf(m0, mx0);
        const float mn1 = fmaxf(m1, mx1);
        const float cr0 = exp2f(m0 - mn0);
        const float cr1 = exp2f(m1 - mn1);
        m0 = mn0; m1 = mn1;

        float ls0 = 0.f, ls1 = 0.f;
#pragma unroll
        for (int ni = 0; ni < 8; ++ni) {
            float p0 = exp2f(s[ni][0] - mn0);
            float p1 = exp2f(s[ni][1] - mn0);
            float p2 = exp2f(s[ni][2] - mn1);
            float p3 = exp2f(s[ni][3] - mn1);
            ls0 += p0 + p1;
            ls1 += p2 + p3;
            Ps[(wrow + gr    ) * 36 + ni * 4 + gc] = packh2(p0, p1);
            Ps[(wrow + gr + 8) * 36 + ni * 4 + gc] = packh2(p2, p3);
        }
        ls0 += __shfl_xor_sync(0xffffffffu, ls0, 1);
        ls0 += __shfl_xor_sync(0xffffffffu, ls0, 2);
        ls1 += __shfl_xor_sync(0xffffffffu, ls1, 1);
        ls1 += __shfl_xor_sync(0xffffffffu, ls1, 2);
        l0 = l0 * cr0 + ls0;
        l1 = l1 * cr1 + ls1;

#pragma unroll
        for (int ni = 0; ni < 16; ++ni) {
            oacc[ni][0] *= cr0; oacc[ni][1] *= cr0;
            oacc[ni][2] *= cr1; oacc[ni][3] *= cr1;
        }
        __syncwarp();

#pragma unroll
        for (int kk = 0; kk < 64; kk += 16) {
            const int wb = kk >> 1;
            unsigned a0 = Ps[(wrow + gr    ) * 36 + wb + gc    ];
            unsigned a1 = Ps[(wrow + gr + 8) * 36 + wb + gc    ];
            unsigned a2 = Ps[(wrow + gr    ) * 36 + wb + gc + 4];
            unsigned a3 = Ps[(wrow + gr + 8) * 36 + wb + gc + 4];
#pragma unroll
            for (int ni = 0; ni < 16; ++ni) {
                unsigned b0 = Vs[(ni * 8 + gr) * 36 + wb + gc    ];
                unsigned b1 = Vs[(ni * 8 + gr) * 36 + wb + gc + 4];
                asm volatile(
                    "mma.sync.aligned.m16n8k16.row.col.f32.f16.f16.f32 "
                    "{%0,%1,%2,%3}, {%4,%5,%6,%7}, {%8,%9}, {%0,%1,%2,%3};"
                    : "+f"(oacc[ni][0]), "+f"(oacc[ni][1]),
                      "+f"(oacc[ni][2]), "+f"(oacc[ni][3])
                    : "r"(a0), "r"(a1), "r"(a2), "r"(a3), "r"(b0), "r"(b1));
            }
        }
    }

    const float i0 = 1.f / l0;
    const float i1 = 1.f / l1;
    const int t0 = qrow0 + wrow + gr;
#pragma unroll
    for (int ni = 0; ni < 16; ++ni) {
        const int d = ni * 8 + gc * 2;
        __half* p0 = AO + ((size_t)(b * cT + t0    ) * cH + h) * cD + d;
        __half* p1 = AO + ((size_t)(b * cT + t0 + 8) * cH + h) * cD + d;
        *(unsigned*)p0 = packh2(oacc[ni][0] * i0, oacc[ni][1] * i0);
        *(unsigned*)p1 = packh2(oacc[ni][2] * i1, oacc[ni][3] * i1);
    }
}

// ---------------------------------------------------------------------------
extern "C" void kernel_launch(void* const* d_in, const int* in_sizes, int n_in,
                              void* d_out, int out_size)
{
    const float* x  = (const float*)d_in[0];
    const float* wq = (const float*)d_in[2];
    const float* wk = (const float*)d_in[3];
    const float* wv = (const float*)d_in[4];
    const float* wo = (const float*)d_in[5];
    float* out = (float*)d_out;

    void *pq, *pk, *pv, *pao, *pxh, *pwc, *pwo;
    cudaGetSymbolAddress(&pq,  g_q);
    cudaGetSymbolAddress(&pk,  g_k);
    cudaGetSymbolAddress(&pv,  g_vt);
    cudaGetSymbolAddress(&pao, g_ao);
    cudaGetSymbolAddress(&pxh, g_xh);
    cudaGetSymbolAddress(&pwc, g_wcat);
    cudaGetSymbolAddress(&pwo, g_wot);
    __half* q    = (__half*)pq;
    __half* k    = (__half*)pk;
    __half* vt   = (__half*)pv;
    __half* ao   = (__half*)pao;
    __half* xh   = (__half*)pxh;
    __half* wcat = (__half*)pwc;
    __half* wot  = (__half*)pwo;

    const int M = cB * cT;  // 4096

    quant_kernel<<<(int)(((size_t)M * cE / 4) / 256), 256>>>(x, xh);
    wtrans_kernel<<<dim3(2048 / 32, 2048 / 32), dim3(32, 8)>>>(wq, wcat, 2048, 2048);
    wtrans_kernel<<<dim3(1024 / 32, 2048 / 32), dim3(32, 8)>>>(wk, wcat + (size_t)2048 * 2048, 2048, 1024);
    wtrans_kernel<<<dim3(1024 / 32, 2048 / 32), dim3(32, 8)>>>(wv, wcat + (size_t)3072 * 2048, 2048, 1024);
    wtrans_kernel<<<dim3(2048 / 32, 2048 / 32), dim3(32, 8)>>>(wo, wot, 2048, 2048);

    const int gemm_smem = 3 * 32768;  // 98304 -> 2 CTAs/SM
    cudaFuncSetAttribute(fp16_gemm, cudaFuncAttributeMaxDynamicSharedMemorySize, gemm_smem);

    // Fused QKV projection
    fp16_gemm<<<dim3(32, 32), 256, gemm_smem>>>(xh, wcat, nullptr, q, k, vt, 4096, cE, 3);

    const int attn_smem = (128 * 68 + 64 * 68 + 128 * 36 + 128 * 36) * 4;  // 89088
    cudaFuncSetAttribute(attn_kernel, cudaFuncAttributeMaxDynamicSharedMemorySize, attn_smem);
    attn_kernel<<<cB * cH * (cT / 128), 256, attn_smem>>>(q, k, vt, ao);

    // Output projection
    fp16_gemm<<<dim3(16, 32), 256, gemm_smem>>>(ao, wot, out, nullptr, nullptr, nullptr, cE, cE, 0);
}

// round 17
// speedup vs baseline: 1.6670x; 1.1020x over previous
#include <cuda_runtime.h>
#include <cuda_fp16.h>
#include <math.h>
#include <cstdint>

constexpr int cB   = 2;
constexpr int cT   = 2048;
constexpr int cE   = 2048;
constexpr int cH   = 16;
constexpr int cKVH = 8;
constexpr int cD   = 128;

// Scratch (device globals). Half-precision operand buffers.
__device__ __half g_q   [(size_t)cB * cH   * cT * cD];   // (b,h,t,d) roped
__device__ __half g_k   [(size_t)cB * cKVH * cT * cD];   // (b,kvh,t,d) roped
__device__ __half g_vt  [(size_t)cB * cKVH * cD * cT];   // (b,kvh,d,t)
__device__ __half g_ao  [(size_t)cB * cT * cH * cD];     // (b,t,h,d)
__device__ __half g_xh  [(size_t)cB * cT * cE];          // x in half
// Concatenated transposed weights: rows [0,2048)=wq^T, [2048,3072)=wk^T, [3072,4096)=wv^T
__device__ __half g_wcat[(size_t)4096 * 2048];
__device__ __half g_wot [(size_t)2048 * 2048];

__device__ __forceinline__ uint32_t smem_u32(const void* p) {
    uint32_t a;
    asm("{ .reg .u64 t; cvta.to.shared.u64 t, %1; cvt.u32.u64 %0, t; }" : "=r"(a) : "l"(p));
    return a;
}

__device__ __forceinline__ void cp16(uint32_t dst, const void* src) {
    asm volatile("cp.async.cg.shared.global [%0], [%1], 16;"
                 :: "r"(dst), "l"(src) : "memory");
}

__device__ __forceinline__ unsigned packh2(float a, float b) {
    __half2 h = __floats2half2_rn(a, b);
    return *(unsigned*)&h;
}

// ---------------------------------------------------------------------------
__global__ __launch_bounds__(256) void quant_kernel(
    const float* __restrict__ x, __half* __restrict__ xh)
{
    const size_t i = ((size_t)blockIdx.x * 256 + threadIdx.x) * 4;
    float4 v = *(const float4*)(x + i);
    unsigned lo = packh2(v.x, v.y);
    unsigned hi = packh2(v.z, v.w);
    *(uint2*)(xh + i) = make_uint2(lo, hi);
}

// ---------------------------------------------------------------------------
__global__ __launch_bounds__(256) void wtrans_kernel(
    const float* __restrict__ W, __half* __restrict__ WT, int R, int Cc)
{
    __shared__ unsigned short t[32][33];
    const int x = blockIdx.x * 32 + threadIdx.x;
    const int y0 = blockIdx.y * 32 + threadIdx.y;
#pragma unroll
    for (int i = 0; i < 4; ++i) {
        __half h = __float2half_rn(W[(size_t)(y0 + i * 8) * Cc + x]);
        t[threadIdx.y + i * 8][threadIdx.x] = *(unsigned short*)&h;
    }
    __syncthreads();
    const int xo = blockIdx.y * 32 + threadIdx.x;
    const int yo0 = blockIdx.x * 32 + threadIdx.y;
#pragma unroll
    for (int i = 0; i < 4; ++i) {
        unsigned short v = t[threadIdx.x][threadIdx.y + i * 8];
        WT[(size_t)(yo0 + i * 8) * R + xo] = *(__half*)&v;
    }
}

// ---------------------------------------------------------------------------
// FP16 mma.sync GEMM v4 (R13 — passing, 2 CTA/SM). Unchanged.
// ---------------------------------------------------------------------------
__device__ __forceinline__ void gemm4_load_stage(
    uint32_t sb, int s, int kt,
    const __half* __restrict__ A, const __half* __restrict__ BT,
    int rowBase, int colBase, int K, int lr, int lcc, int chS)
{
    const uint32_t aBase = sb + (uint32_t)s * 32768u;
    const uint32_t bBase = aBase + 16384u;
#pragma unroll
    for (int c = 0; c < 4; ++c) {
        const int row = lr + c * 32;
        cp16(aBase + (uint32_t)(row * 128 + chS * 16),
             A + (size_t)(rowBase + row) * K + kt + lcc * 8);
        cp16(bBase + (uint32_t)(row * 128 + chS * 16),
             BT + (size_t)(colBase + row) * K + kt + lcc * 8);
    }
    asm volatile("cp.async.commit_group;" ::: "memory");
}

__global__ __launch_bounds__(256) void fp16_gemm(
    const __half* __restrict__ A, const __half* __restrict__ BT,
    void* __restrict__ Cv,
    __half* __restrict__ Qo, __half* __restrict__ Ko, __half* __restrict__ Vo,
    int N, int K, int mode)
{
    extern __shared__ unsigned smp[];
    const uint32_t sb = smem_u32(smp);

    const int tid  = threadIdx.x;
    const int lane = tid & 31;
    const int w    = tid >> 5;
    const int wm   = (w >> 2) * 64;
    const int wn   = (w & 3) * 32;
    const int gr   = lane >> 2;
    const int gc   = lane & 3;

    const int rowBase = blockIdx.y * 128;
    const int colBase = blockIdx.x * 128;

    const int lr  = tid >> 3;
    const int lcc = tid & 7;
    const int chS = (lcc + (lr & 7)) & 7;

    float acc[4][4][4];
#pragma unroll
    for (int mi = 0; mi < 4; ++mi)
#pragma unroll
        for (int ni = 0; ni < 4; ++ni)
#pragma unroll
            for (int c = 0; c < 4; ++c) acc[mi][ni][c] = 0.f;

    const int nch = K / 64;
    gemm4_load_stage(sb, 0, 0,  A, BT, rowBase, colBase, K, lr, lcc, chS);
    gemm4_load_stage(sb, 1, 64, A, BT, rowBase, colBase, K, lr, lcc, chS);

    for (int ck = 0; ck < nch; ++ck) {
        const int s = ck % 3;
        if (ck + 2 < nch)
            asm volatile("cp.async.wait_group 1;" ::: "memory");
        else
            asm volatile("cp.async.wait_group 0;" ::: "memory");
        __syncthreads();
        if (ck + 2 < nch)
            gemm4_load_stage(sb, (ck + 2) % 3, (ck + 2) * 64,
                             A, BT, rowBase, colBase, K, lr, lcc, chS);

        const unsigned* As = smp + s * 8192;
        const unsigned* Bs = As + 4096;
#pragma unroll
        for (int kk = 0; kk < 64; kk += 16) {
            const int ch0 = kk >> 3;
            const int sw0 = (((ch0    ) + gr) & 7) * 4 + gc;
            const int sw1 = (((ch0 + 1) + gr) & 7) * 4 + gc;
            unsigned af[4][4], bf[4][2];
#pragma unroll
            for (int mi = 0; mi < 4; ++mi) {
                const int r = wm + mi * 16 + gr;
                af[mi][0] = As[r * 32 + sw0];
                af[mi][1] = As[(r + 8) * 32 + sw0];
                af[mi][2] = As[r * 32 + sw1];
                af[mi][3] = As[(r + 8) * 32 + sw1];
            }
#pragma unroll
            for (int ni = 0; ni < 4; ++ni) {
                const int rN = wn + ni * 8 + gr;
                bf[ni][0] = Bs[rN * 32 + sw0];
                bf[ni][1] = Bs[rN * 32 + sw1];
            }
#pragma unroll
            for (int mi = 0; mi < 4; ++mi)
#pragma unroll
                for (int ni = 0; ni < 4; ++ni) {
                    asm volatile(
                        "mma.sync.aligned.m16n8k16.row.col.f32.f16.f16.f32 "
                        "{%0,%1,%2,%3}, {%4,%5,%6,%7}, {%8,%9}, {%0,%1,%2,%3};"
                        : "+f"(acc[mi][ni][0]), "+f"(acc[mi][ni][1]),
                          "+f"(acc[mi][ni][2]), "+f"(acc[mi][ni][3])
                        : "r"(af[mi][0]), "r"(af[mi][1]),
                          "r"(af[mi][2]), "r"(af[mi][3]),
                          "r"(bf[ni][0]), "r"(bf[ni][1]));
                }
        }
    }

    if (mode == 0) {
        float* C = (float*)Cv;
#pragma unroll
        for (int mi = 0; mi < 4; ++mi)
#pragma unroll
            for (int ni = 0; ni < 4; ++ni) {
                const int row0 = rowBase + wm + mi * 16 + gr;
                const int col  = colBase + wn + ni * 8 + gc * 2;
                *(float2*)(C + (size_t)row0 * N + col) =
                    make_float2(acc[mi][ni][0], acc[mi][ni][1]);
                *(float2*)(C + (size_t)(row0 + 8) * N + col) =
                    make_float2(acc[mi][ni][2], acc[mi][ni][3]);
            }
        return;
    }

    const int hcat = colBase >> 7;
    if (hcat < 24) {
        __half* OutP = (hcat < 16) ? Qo : Ko;
        const int HH  = (hcat < 16) ? cH : cKVH;
        const int h   = (hcat < 16) ? hcat : hcat - 16;
#pragma unroll
        for (int mi = 0; mi < 4; ++mi)
#pragma unroll
            for (int ni = 0; ni < 4; ++ni) {
                const int row0 = rowBase + wm + mi * 16 + gr;
                const int col  = colBase + wn + ni * 8 + gc * 2;
                const int d = col & (cD - 1);
                const int j = d >> 1;
                const float inv = exp2f(-13.287712379549449f * (float)j * (1.0f / 64.0f));
#pragma unroll
                for (int rr = 0; rr < 2; ++rr) {
                    const int row = row0 + rr * 8;
                    const int b = row >> 11;
                    const int t = row & (cT - 1);
                    float sn, cs;
                    sincosf((float)t * inv, &sn, &cs);
                    const float x0 = acc[mi][ni][rr*2];
                    const float x1 = acc[mi][ni][rr*2+1];
                    __half* p = OutP + ((size_t)(b * HH + h) * cT + t) * cD + d;
                    *(unsigned*)p = packh2(x0 * cs - x1 * sn, x0 * sn + x1 * cs);
                }
            }
    } else {
        const int h = hcat - 24;
#pragma unroll
        for (int mi = 0; mi < 4; ++mi)
#pragma unroll
            for (int ni = 0; ni < 4; ++ni) {
                const int row0 = rowBase + wm + mi * 16 + gr;
                const int col  = colBase + wn + ni * 8 + gc * 2;
                const int d = col & (cD - 1);
#pragma unroll
                for (int rr = 0; rr < 2; ++rr) {
                    const int row = row0 + rr * 8;
                    const int b = row >> 11;
                    const int t = row & (cT - 1);
                    __half* p = Vo + ((size_t)(b * cKVH + h) * cD + d) * cT + t;
                    p[0]  = __float2half_rn(acc[mi][ni][rr*2]);
                    p[cT] = __float2half_rn(acc[mi][ni][rr*2+1]);
                }
            }
    }
}

// ---------------------------------------------------------------------------
// FP16 flash attention: R16 base + P kept in registers (no Ps smem buffer).
// __launch_bounds__(256, 2) pins 2 CTAs/SM (<=128 regs enforced by ptxas).
// smem: Qs 128x68w + Ks 64x68w + Vs 128x36w = 17664 words = 70656 B
// ---------------------------------------------------------------------------
__global__ __launch_bounds__(256, 2) void attn_kernel(
    const __half* __restrict__ Q, const __half* __restrict__ K,
    const __half* __restrict__ VT, __half* __restrict__ AO)
{
    extern __shared__ unsigned sm[];
    unsigned* Qs = sm;                        // [128][68] words
    unsigned* Ks = Qs + 128 * 68;             // [64][68]
    unsigned* Vs = Ks + 64 * 68;              // [128][36]
    const uint32_t sQ = smem_u32(Qs);
    const uint32_t sK = smem_u32(Ks);
    const uint32_t sV = smem_u32(Vs);

    const int bid = blockIdx.x;
    const int qb  = 15 - (bid & 15);          // LPT: heavy q-blocks first
    const int h   = (bid >> 4) & 15;
    const int b   = bid >> 8;
    const int kvh = h >> 1;

    const __half* qptr  = Q  + ((size_t)(b * cH + h) * cT + qb * 128) * cD;
    const __half* kbase = K  + (size_t)(b * cKVH + kvh) * cT * cD;
    const __half* vbase = VT + (size_t)(b * cKVH + kvh) * cD * cT;

    const int tid  = threadIdx.x;
    const int lane = tid & 31;
    const int w    = tid >> 5;
    const int gr   = lane >> 2;
    const int gc   = lane & 3;
    const int wrow = w * 16;

#pragma unroll
    for (int it = 0; it < 8; ++it) {
        const int i = tid + it * 256;
        const int r = i >> 4, c16 = i & 15;
        cp16(sQ + (uint32_t)(r * 272 + c16 * 16), qptr + (size_t)r * cD + c16 * 8);
    }
    asm volatile("cp.async.commit_group;" ::: "memory");

    float m0 = -1e30f, m1 = -1e30f, l0 = 0.f, l1 = 0.f;
    float oacc[16][4];
#pragma unroll
    for (int ni = 0; ni < 16; ++ni)
#pragma unroll
        for (int c = 0; c < 4; ++c) oacc[ni][c] = 0.f;

    const float sc = 0.08838834764831845f * 1.4426950408889634f;
    const int qrow0 = qb * 128;
    const int nkv = 2 * qb + 2;

    for (int kt = 0; kt < nkv; ++kt) {
        __syncthreads();
        const __half* kp = kbase + (size_t)kt * 64 * cD;
        const __half* vp = vbase + kt * 64;
#pragma unroll
        for (int it = 0; it < 4; ++it) {
            const int i = tid + it * 256;
            {
                const int r = i >> 4, c16 = i & 15;
                cp16(sK + (uint32_t)(r * 272 + c16 * 16), kp + (size_t)r * cD + c16 * 8);
            }
            {
                const int d = i >> 3, c8 = i & 7;
                cp16(sV + (uint32_t)(d * 144 + c8 * 16), vp + (size_t)d * cT + c8 * 8);
            }
        }
        asm volatile("cp.async.commit_group;" ::: "memory");
        asm volatile("cp.async.wait_group 0;" ::: "memory");
        __syncthreads();

        float s[8][4];
#pragma unroll
        for (int ni = 0; ni < 8; ++ni)
#pragma unroll
            for (int c = 0; c < 4; ++c) s[ni][c] = 0.f;

#pragma unroll
        for (int kk = 0; kk < 128; kk += 16) {
            const int wb = kk >> 1;
            unsigned a0 = Qs[(wrow + gr    ) * 68 + wb + gc    ];
            unsigned a1 = Qs[(wrow + gr + 8) * 68 + wb + gc    ];
            unsigned a2 = Qs[(wrow + gr    ) * 68 + wb + gc + 4];
            unsigned a3 = Qs[(wrow + gr + 8) * 68 + wb + gc + 4];
#pragma unroll
            for (int ni = 0; ni < 8; ++ni) {
                unsigned b0 = Ks[(ni * 8 + gr) * 68 + wb + gc    ];
                unsigned b1 = Ks[(ni * 8 + gr) * 68 + wb + gc + 4];
                asm volatile(
                    "mma.sync.aligned.m16n8k16.row.col.f32.f16.f16.f32 "
                    "{%0,%1,%2,%3}, {%4,%5,%6,%7}, {%8,%9}, {%0,%1,%2,%3};"
                    : "+f"(s[ni][0]), "+f"(s[ni][1]), "+f"(s[ni][2]), "+f"(s[ni][3])
                    : "r"(a0), "r"(a1), "r"(a2), "r"(a3), "r"(b0), "r"(b1));
            }
        }

        const bool diag = (kt >= 2 * qb);
        const int r0g = qrow0 + wrow + gr;
        const int r1g = r0g + 8;
#pragma unroll
        for (int ni = 0; ni < 8; ++ni) {
            const int col = kt * 64 + ni * 8 + gc * 2;
            s[ni][0] = (diag && col     > r0g) ? -1e30f : s[ni][0] * sc;
            s[ni][1] = (diag && col + 1 > r0g) ? -1e30f : s[ni][1] * sc;
            s[ni][2] = (diag && col     > r1g) ? -1e30f : s[ni][2] * sc;
            s[ni][3] = (diag && col + 1 > r1g) ? -1e30f : s[ni][3] * sc;
        }

        float mx0 = -1e30f, mx1 = -1e30f;
#pragma unroll
        for (int ni = 0; ni < 8; ++ni) {
            mx0 = fmaxf(mx0, fmaxf(s[ni][0], s[ni][1]));
            mx1 = fmaxf(mx1, fmaxf(s[ni][2], s[ni][3]));
        }
        mx0 = fmaxf(mx0, __shfl_xor_sync(0xffffffffu, mx0, 1));
        mx0 = fmaxf(mx0, __shfl_xor_sync(0xffffffffu, mx0, 2));
        mx1 = fmaxf(mx1, __shfl_xor_sync(0xffffffffu, mx1, 1));
        mx1 = fmaxf(mx1, __shfl_xor_sync(0xffffffffu, mx1, 2));

        const float mn0 = fmaxf(m0, mx0);
        const float mn1 = fmaxf(m1, mx1);
        const float cr0 = exp2f(m0 - mn0);
        const float cr1 = exp2f(m1 - mn1);
        m0 = mn0; m1 = mn1;

        // exp + pack P directly into mma A-fragments (registers, no smem)
        unsigned pp[8][2];
        float ls0 = 0.f, ls1 = 0.f;
#pragma unroll
        for (int ni = 0; ni < 8; ++ni) {
            float p0 = exp2f(s[ni][0] - mn0);
            float p1 = exp2f(s[ni][1] - mn0);
            float p2 = exp2f(s[ni][2] - mn1);
            float p3 = exp2f(s[ni][3] - mn1);
            ls0 += p0 + p1;
            ls1 += p2 + p3;
            pp[ni][0] = packh2(p0, p1);
            pp[ni][1] = packh2(p2, p3);
        }
        ls0 += __shfl_xor_sync(0xffffffffu, ls0, 1);
        ls0 += __shfl_xor_sync(0xffffffffu, ls0, 2);
        ls1 += __shfl_xor_sync(0xffffffffu, ls1, 1);
        ls1 += __shfl_xor_sync(0xffffffffu, ls1, 2);
        l0 = l0 * cr0 + ls0;
        l1 = l1 * cr1 + ls1;

#pragma unroll
        for (int ni = 0; ni < 16; ++ni) {
            oacc[ni][0] *= cr0; oacc[ni][1] *= cr0;
            oacc[ni][2] *= cr1; oacc[ni][3] *= cr1;
        }

        // O += P V : P from registers, V^T from smem
#pragma unroll
        for (int kk = 0; kk < 64; kk += 16) {
            const int wb = kk >> 1;
            const int f0 = kk >> 3;          // 0,2,4,6
            unsigned a0 = pp[f0][0];
            unsigned a1 = pp[f0][1];
            unsigned a2 = pp[f0 + 1][0];
            unsigned a3 = pp[f0 + 1][1];
#pragma unroll
            for (int ni = 0; ni < 16; ++ni) {
                unsigned b0 = Vs[(ni * 8 + gr) * 36 + wb + gc    ];
                unsigned b1 = Vs[(ni * 8 + gr) * 36 + wb + gc + 4];
                asm volatile(
                    "mma.sync.aligned.m16n8k16.row.col.f32.f16.f16.f32 "
                    "{%0,%1,%2,%3}, {%4,%5,%6,%7}, {%8,%9}, {%0,%1,%2,%3};"
                    : "+f"(oacc[ni][0]), "+f"(oacc[ni][1]),
                      "+f"(oacc[ni][2]), "+f"(oacc[ni][3])
                    : "r"(a0), "r"(a1), "r"(a2), "r"(a3), "r"(b0), "r"(b1));
            }
        }
    }

    const float i0 = 1.f / l0;
    const float i1 = 1.f / l1;
    const int t0 = qrow0 + wrow + gr;
#pragma unroll
    for (int ni = 0; ni < 16; ++ni) {
        const int d = ni * 8 + gc * 2;
        __half* p0 = AO + ((size_t)(b * cT + t0    ) * cH + h) * cD + d;
        __half* p1 = AO + ((size_t)(b * cT + t0 + 8) * cH + h) * cD + d;
        *(unsigned*)p0 = packh2(oacc[ni][0] * i0, oacc[ni][1] * i0);
        *(unsigned*)p1 = packh2(oacc[ni][2] * i1, oacc[ni][3] * i1);
    }
}

// ---------------------------------------------------------------------------
extern "C" void kernel_launch(void* const* d_in, const int* in_sizes, int n_in,
                              void* d_out, int out_size)
{
    const float* x  = (const float*)d_in[0];
    const float* wq = (const float*)d_in[2];
    const float* wk = (const float*)d_in[3];
    const float* wv = (const float*)d_in[4];
    const float* wo = (const float*)d_in[5];
    float* out = (float*)d_out;

    void *pq, *pk, *pv, *pao, *pxh, *pwc, *pwo;
    cudaGetSymbolAddress(&pq,  g_q);
    cudaGetSymbolAddress(&pk,  g_k);
    cudaGetSymbolAddress(&pv,  g_vt);
    cudaGetSymbolAddress(&pao, g_ao);
    cudaGetSymbolAddress(&pxh, g_xh);
    cudaGetSymbolAddress(&pwc, g_wcat);
    cudaGetSymbolAddress(&pwo, g_wot);
    __half* q    = (__half*)pq;
    __half* k    = (__half*)pk;
    __half* vt   = (__half*)pv;
    __half* ao   = (__half*)pao;
    __half* xh   = (__half*)pxh;
    __half* wcat = (__half*)pwc;
    __half* wot  = (__half*)pwo;

    const int M = cB * cT;  // 4096

    quant_kernel<<<(int)(((size_t)M * cE / 4) / 256), 256>>>(x, xh);
    wtrans_kernel<<<dim3(2048 / 32, 2048 / 32), dim3(32, 8)>>>(wq, wcat, 2048, 2048);
    wtrans_kernel<<<dim3(1024 / 32, 2048 / 32), dim3(32, 8)>>>(wk, wcat + (size_t)2048 * 2048, 2048, 1024);
    wtrans_kernel<<<dim3(1024 / 32, 2048 / 32), dim3(32, 8)>>>(wv, wcat + (size_t)3072 * 2048, 2048, 1024);
    wtrans_kernel<<<dim3(2048 / 32, 2048 / 32), dim3(32, 8)>>>(wo, wot, 2048, 2048);

    const int gemm_smem = 3 * 32768;  // 98304 -> 2 CTAs/SM
    cudaFuncSetAttribute(fp16_gemm, cudaFuncAttributeMaxDynamicSharedMemorySize, gemm_smem);

    // Fused QKV projection
    fp16_gemm<<<dim3(32, 32), 256, gemm_smem>>>(xh, wcat, nullptr, q, k, vt, 4096, cE, 3);

    const int attn_smem = (128 * 68 + 64 * 68 + 128 * 36) * 4;  // 70656
    cudaFuncSetAttribute(attn_kernel, cudaFuncAttributeMaxDynamicSharedMemorySize, attn_smem);
    attn_kernel<<<cB * cH * (cT / 128), 256, attn_smem>>>(q, k, vt, ao);

    // Output projection
    fp16_gemm<<<dim3(16, 32), 256, gemm_smem>>>(ao, wot, out, nullptr, nullptr, nullptr, cE, cE, 0);
}